// round 9
// baseline (speedup 1.0000x reference)
#include <cuda_runtime.h>
#include <cuda_bf16.h>

#define FIVE_K 6
#define OUT_N  512
#define IN_N   1024
#define HID_N  32
#define B_N    256
#define HPAD   36   // padded float stride per elem: conflict-free LDS/STS.128

typedef unsigned long long ull;

// ---------------------------------------------------------------------------
// f32x2 packed helpers (FFMA2 — ptxas never emits these from C++)
// ---------------------------------------------------------------------------
__device__ __forceinline__ ull pack2(float a, float b) {
    ull r;
    asm("mov.b64 %0, {%1, %2};"
        : "=l"(r) : "r"(__float_as_uint(a)), "r"(__float_as_uint(b)));
    return r;
}
__device__ __forceinline__ ull pdup(float a) {
    ull r;
    asm("mov.b64 %0, {%1, %1};" : "=l"(r) : "r"(__float_as_uint(a)));
    return r;
}
__device__ __forceinline__ void fma2(ull& d, ull a, ull b) {
    asm("fma.rn.f32x2 %0, %1, %2, %0;" : "+l"(d) : "l"(a), "l"(b));
}
__device__ __forceinline__ void unpack2(ull v, float& lo, float& hi) {
    unsigned ulo, uhi;
    asm("mov.b64 {%0, %1}, %2;" : "=r"(ulo), "=r"(uhi) : "l"(v));
    lo = __uint_as_float(ulo);
    hi = __uint_as_float(uhi);
}
__device__ __forceinline__ float4 relu4(ull p0, ull p1) {
    float l0, h0, l1, h1;
    unpack2(p0, l0, h0);
    unpack2(p1, l1, h1);
    return make_float4(fmaxf(l0, 0.f), fmaxf(h0, 0.f),
                       fmaxf(l1, 0.f), fmaxf(h1, 0.f));
}

// ---------------------------------------------------------------------------
// topk machinery: 64-bit keys (orderable_float << 10) | (1023 - idx)
// (validated rel_err 0.0 since R4 — network unchanged)
// ---------------------------------------------------------------------------
__device__ __forceinline__ ull mk_key(float x, int gi) {
    unsigned u = __float_as_uint(x);
    unsigned ord = (u & 0x80000000u) ? ~u : (u | 0x80000000u);
    return ((ull)ord << 10) | (ull)(1023 - gi);
}
__device__ __forceinline__ void cas(ull& a, ull& b) {
    ull hi = a > b ? a : b;
    ull lo = a > b ? b : a;
    a = hi; b = lo;
}
__device__ __forceinline__ ull mx(ull a, ull b) { return a > b ? a : b; }

__device__ __forceinline__ void sort6(ull* t) {
    cas(t[0], t[1]); cas(t[2], t[3]); cas(t[4], t[5]);
    cas(t[0], t[2]); cas(t[1], t[3]);
    cas(t[1], t[2]);
    cas(t[0], t[4]); cas(t[1], t[5]);
    cas(t[2], t[4]); cas(t[3], t[5]);
    cas(t[1], t[2]); cas(t[3], t[4]);
}
__device__ __forceinline__ void merge6(ull* a, const ull* b) {
    ull t[6];
    t[0] = mx(a[0], b[5]); t[1] = mx(a[1], b[4]); t[2] = mx(a[2], b[3]);
    t[3] = mx(a[3], b[2]); t[4] = mx(a[4], b[1]); t[5] = mx(a[5], b[0]);
    sort6(t);
#pragma unroll
    for (int q = 0; q < 6; q++) a[q] = t[q];
}
__device__ __forceinline__ void sort4(ull& a0, ull& a1, ull& a2, ull& a3) {
    cas(a0, a1); cas(a2, a3); cas(a0, a2); cas(a1, a3); cas(a1, a2);
}

// ---------------------------------------------------------------------------
// Fused kernel: one block (256 threads) per unit o.
// Thread = (half = tid>>7, bidx = tid&127): computes outputs
// [half*16, half*16+16) for batch elements bidx and bidx+128.
// acc liveness halves (8 ull per elem) -> ~80 regs -> 3 blocks/SM, 24 warps.
// Activations parked in smem [elem][HPAD]; 3 syncthreads exchange halves.
// ---------------------------------------------------------------------------
__global__ __launch_bounds__(256, 3)
void blayer_fused(const float* __restrict__ inputs,
                  const float* __restrict__ mask,
                  const float* __restrict__ W1,
                  const float* __restrict__ W2,
                  const float* __restrict__ W3,
                  const float* __restrict__ W4,
                  float* __restrict__ out)
{
    __shared__ float sH[B_N * HPAD];        // 36.9 KB, [elem][36]
    __shared__ float sW1[FIVE_K * HID_N];
    __shared__ float sW2[HID_N * HID_N];
    __shared__ float sW3[HID_N * HID_N];
    __shared__ float sW4[HID_N];
    __shared__ ull   sLists[8][6];
    __shared__ int   sIdx[FIVE_K];

    const int o    = blockIdx.x;
    const int tid  = threadIdx.x;
    const int warp = tid >> 5;
    const int lane = tid & 31;
    const int half = tid >> 7;      // 0: outs 0-15, 1: outs 16-31
    const int bidx = tid & 127;     // batch elems bidx, bidx+128

    // -- prefetch dense weights into registers (hides under topk) --
    float4 r2 = reinterpret_cast<const float4*>(W2 + o * HID_N * HID_N)[tid];
    float4 r3 = reinterpret_cast<const float4*>(W3 + o * HID_N * HID_N)[tid];
    float  w4r = (tid < HID_N) ? W4[o * HID_N + tid] : 0.f;

    // -- cooperative top-6 of mask row o: 4 values per thread --
    float4 m = reinterpret_cast<const float4*>(mask + o * IN_N)[tid];

    ull a[6], bl[6];
    {
        ull k0 = mk_key(m.x, 4 * tid + 0);
        ull k1 = mk_key(m.y, 4 * tid + 1);
        ull k2 = mk_key(m.z, 4 * tid + 2);
        ull k3 = mk_key(m.w, 4 * tid + 3);
        sort4(k0, k1, k2, k3);
        a[0] = k0; a[1] = k1; a[2] = k2; a[3] = k3; a[4] = 0; a[5] = 0;
    }
#pragma unroll
    for (int off = 16; off >= 1; off >>= 1) {
#pragma unroll
        for (int j = 0; j < 6; j++)
            bl[j] = __shfl_xor_sync(0xFFFFFFFFu, a[j], off);
        merge6(a, bl);
    }
    if (lane == 0) {
#pragma unroll
        for (int j = 0; j < 6; j++) sLists[warp][j] = a[j];
    }

    // -- stage dense weights to smem --
    reinterpret_cast<float4*>(sW2)[tid] = r2;
    reinterpret_cast<float4*>(sW3)[tid] = r3;
    if (tid < HID_N) sW4[tid] = w4r;
    __syncthreads();

    // -- warp 0 merges the 8 warp lists (own list still in registers) --
    if (warp == 0) {
#pragma unroll
        for (int w = 1; w < 8; w++) {
#pragma unroll
            for (int j = 0; j < 6; j++) bl[j] = sLists[w][j];
            merge6(a, bl);
        }
        if (lane == 0) {
#pragma unroll
            for (int j = 0; j < 6; j++)
                sIdx[j] = 1023 - (int)(a[j] & 1023ull);
        }
    }
    __syncthreads();

    // -- W1 rows + the 6 input values for my two batch elements --
    if (tid < FIVE_K * HID_N) {
        int j = tid >> 5, k = tid & 31;
        sW1[tid] = W1[(o * IN_N + sIdx[j]) * HID_N + k];
    }
    float xA[FIVE_K], xB[FIVE_K];
#pragma unroll
    for (int j = 0; j < FIVE_K; j++) {
        int ix = sIdx[j];
        xA[j] = inputs[bidx * IN_N + ix];
        xB[j] = inputs[(bidx + 128) * IN_N + ix];
    }
    __syncthreads();

    // per-elem h views; my write slot = float4s [half*4, half*4+4)
    float4* hA4 = reinterpret_cast<float4*>(sH) + bidx * (HPAD / 4);
    float4* hB4 = reinterpret_cast<float4*>(sH) + (bidx + 128) * (HPAD / 4);
    const int wslot = half * 4;
    const int wseg  = half * 16;    // my 16-float weight-column segment

    ull acc[16];    // [0..7] elem A, [8..15] elem B  (16 outputs each)

    // ---- layer 1: 6 -> 32 (my 16 outputs) ----
#pragma unroll
    for (int q = 0; q < 16; q++) acc[q] = 0ull;
#pragma unroll
    for (int r = 0; r < FIVE_K; r++) {
        const ulonglong2* wr =
            reinterpret_cast<const ulonglong2*>(sW1 + r * HID_N + wseg);
        ulonglong2 wa = wr[0], wb = wr[1];
        ull dA = pdup(xA[r]), dB = pdup(xB[r]);
        fma2(acc[0], dA, wa.x); fma2(acc[1], dA, wa.y);
        fma2(acc[2], dA, wb.x); fma2(acc[3], dA, wb.y);
        fma2(acc[8], dB, wa.x); fma2(acc[9], dB, wa.y);
        fma2(acc[10], dB, wb.x); fma2(acc[11], dB, wb.y);
        ulonglong2 wc = wr[2], wd = wr[3];
        fma2(acc[4], dA, wc.x); fma2(acc[5], dA, wc.y);
        fma2(acc[6], dA, wd.x); fma2(acc[7], dA, wd.y);
        fma2(acc[12], dB, wc.x); fma2(acc[13], dB, wc.y);
        fma2(acc[14], dB, wd.x); fma2(acc[15], dB, wd.y);
    }
#pragma unroll
    for (int q = 0; q < 4; q++) {
        hA4[wslot + q] = relu4(acc[2 * q],     acc[2 * q + 1]);
        hB4[wslot + q] = relu4(acc[8 + 2 * q], acc[8 + 2 * q + 1]);
    }
    __syncthreads();

    // ---- layers 2 & 3: 32 -> 32 (my 16 outputs), h streamed in 8-chunks ----
#pragma unroll
    for (int L = 0; L < 2; L++) {
        const float* SW = (L == 0) ? sW2 : sW3;
#pragma unroll
        for (int q = 0; q < 16; q++) acc[q] = 0ull;
#pragma unroll
        for (int rb = 0; rb < 4; rb++) {
            float4 ca0 = hA4[rb * 2], ca1 = hA4[rb * 2 + 1];
            float4 cb0 = hB4[rb * 2], cb1 = hB4[rb * 2 + 1];
            float ha[8] = { ca0.x, ca0.y, ca0.z, ca0.w,
                            ca1.x, ca1.y, ca1.z, ca1.w };
            float hb[8] = { cb0.x, cb0.y, cb0.z, cb0.w,
                            cb1.x, cb1.y, cb1.z, cb1.w };
#pragma unroll
            for (int r8 = 0; r8 < 8; r8++) {
                const ulonglong2* wr = reinterpret_cast<const ulonglong2*>(
                    SW + (rb * 8 + r8) * HID_N + wseg);
                ulonglong2 wa = wr[0], wb = wr[1];
                ull dA = pdup(ha[r8]), dB = pdup(hb[r8]);
                fma2(acc[0], dA, wa.x); fma2(acc[1], dA, wa.y);
                fma2(acc[2], dA, wb.x); fma2(acc[3], dA, wb.y);
                fma2(acc[8], dB, wa.x); fma2(acc[9], dB, wa.y);
                fma2(acc[10], dB, wb.x); fma2(acc[11], dB, wb.y);
                ulonglong2 wc = wr[2], wd = wr[3];
                fma2(acc[4], dA, wc.x); fma2(acc[5], dA, wc.y);
                fma2(acc[6], dA, wd.x); fma2(acc[7], dA, wd.y);
                fma2(acc[12], dB, wc.x); fma2(acc[13], dB, wc.y);
                fma2(acc[14], dB, wd.x); fma2(acc[15], dB, wd.y);
            }
        }
        __syncthreads();    // everyone done READING h of this layer
#pragma unroll
        for (int q = 0; q < 4; q++) {
            hA4[wslot + q] = relu4(acc[2 * q],     acc[2 * q + 1]);
            hB4[wslot + q] = relu4(acc[8 + 2 * q], acc[8 + 2 * q + 1]);
        }
        __syncthreads();    // new h visible to both halves
    }

    // ---- layer 4: one elem per thread (elem = tid), sign of logit ----
    const float4* he = reinterpret_cast<const float4*>(sH) + tid * (HPAD / 4);
    const ull* w4u = reinterpret_cast<const ull*>(sW4);
    ull s = 0ull;
#pragma unroll
    for (int q = 0; q < 8; q++) {
        float4 hh = he[q];
        fma2(s, pack2(hh.x, hh.y), w4u[2 * q]);
        fma2(s, pack2(hh.z, hh.w), w4u[2 * q + 1]);
    }
    float l0, l1;
    unpack2(s, l0, l1);
    float z = l0 + l1;

    out[tid * OUT_N + o] = (z >= 0.f) ? 1.f : -1.f;
}

// ---------------------------------------------------------------------------
extern "C" void kernel_launch(void* const* d_in, const int* in_sizes, int n_in,
                              void* d_out, int out_size)
{
    const float* inputs = (const float*)d_in[0];  // (B, IN)
    const float* mask   = (const float*)d_in[1];  // (OUT, IN)
    const float* W1     = (const float*)d_in[2];  // (OUT, IN, HID)
    const float* W2     = (const float*)d_in[3];  // (OUT, HID, HID)
    const float* W3     = (const float*)d_in[4];  // (OUT, HID, HID)
    const float* W4     = (const float*)d_in[5];  // (OUT, HID, 1)
    float* out = (float*)d_out;                   // (B, OUT)

    static bool attr_set = false;
    if (!attr_set) {
        cudaFuncSetAttribute(blayer_fused,
                             cudaFuncAttributePreferredSharedMemoryCarveout,
                             cudaSharedmemCarveoutMaxShared);
        attr_set = true;
    }

    blayer_fused<<<OUT_N, 256>>>(inputs, mask, W1, W2, W3, W4, out);
}

// round 10
// speedup vs baseline: 1.3792x; 1.3792x over previous
#include <cuda_runtime.h>
#include <cuda_bf16.h>

#define FIVE_K 6
#define OUT_N  512
#define IN_N   1024
#define HID_N  32
#define B_N    256

typedef unsigned long long ull;

// ---------------------------------------------------------------------------
// f32x2 packed helpers (FFMA2 — ptxas never emits these from C++)
// ---------------------------------------------------------------------------
__device__ __forceinline__ ull pack2(float a, float b) {
    ull r;
    asm("mov.b64 %0, {%1, %2};"
        : "=l"(r) : "r"(__float_as_uint(a)), "r"(__float_as_uint(b)));
    return r;
}
__device__ __forceinline__ ull pdup(float a) {
    ull r;
    asm("mov.b64 %0, {%1, %1};" : "=l"(r) : "r"(__float_as_uint(a)));
    return r;
}
__device__ __forceinline__ void fma2(ull& d, ull a, ull b) {
    asm("fma.rn.f32x2 %0, %1, %2, %0;" : "+l"(d) : "l"(a), "l"(b));
}
__device__ __forceinline__ void unpack2(ull v, float& lo, float& hi) {
    unsigned ulo, uhi;
    asm("mov.b64 {%0, %1}, %2;" : "=r"(ulo), "=r"(uhi) : "l"(v));
    lo = __uint_as_float(ulo);
    hi = __uint_as_float(uhi);
}

// cp.async: 16B global -> shared, zero register footprint for the data
__device__ __forceinline__ unsigned smem_u32(const void* p) {
    return (unsigned)__cvta_generic_to_shared(p);
}
__device__ __forceinline__ void cp_async16(unsigned dst, const void* src) {
    asm volatile("cp.async.cg.shared.global [%0], [%1], 16;"
                 :: "r"(dst), "l"(src));
}
__device__ __forceinline__ void cp_async_wait_all() {
    asm volatile("cp.async.commit_group;");
    asm volatile("cp.async.wait_group 0;" ::: "memory");
}

// ---------------------------------------------------------------------------
// topk machinery: 64-bit keys (orderable_float << 10) | (1023 - idx)
// (validated rel_err 0.0 since R4 — unchanged)
// ---------------------------------------------------------------------------
__device__ __forceinline__ ull mk_key(float x, int gi) {
    unsigned u = __float_as_uint(x);
    unsigned ord = (u & 0x80000000u) ? ~u : (u | 0x80000000u);
    return ((ull)ord << 10) | (ull)(1023 - gi);
}
__device__ __forceinline__ void cas(ull& a, ull& b) {
    ull hi = a > b ? a : b;
    ull lo = a > b ? b : a;
    a = hi; b = lo;
}
__device__ __forceinline__ ull mx(ull a, ull b) { return a > b ? a : b; }

__device__ __forceinline__ void sort6(ull* t) {
    cas(t[0], t[1]); cas(t[2], t[3]); cas(t[4], t[5]);
    cas(t[0], t[2]); cas(t[1], t[3]);
    cas(t[1], t[2]);
    cas(t[0], t[4]); cas(t[1], t[5]);
    cas(t[2], t[4]); cas(t[3], t[5]);
    cas(t[1], t[2]); cas(t[3], t[4]);
}
__device__ __forceinline__ void merge6(ull* a, const ull* b) {
    ull t[6];
    t[0] = mx(a[0], b[5]); t[1] = mx(a[1], b[4]); t[2] = mx(a[2], b[3]);
    t[3] = mx(a[3], b[2]); t[4] = mx(a[4], b[1]); t[5] = mx(a[5], b[0]);
    sort6(t);
#pragma unroll
    for (int q = 0; q < 6; q++) a[q] = t[q];
}
__device__ __forceinline__ void sort4(ull& a0, ull& a1, ull& a2, ull& a3) {
    cas(a0, a1); cas(a2, a3); cas(a0, a2); cas(a1, a3); cas(a1, a2);
}

// ---------------------------------------------------------------------------
// One batch element through the 4-layer MLP (packed f32x2, single acc set).
// Peak liveness: h[32] + acc[16 ull] + weight regs ≈ 105.
// ---------------------------------------------------------------------------
__device__ __forceinline__ float mlp_one(const float* __restrict__ sW1,
                                         const float* __restrict__ sW2,
                                         const float* __restrict__ sW3,
                                         const float* __restrict__ sW4,
                                         const float* x)
{
    float h[HID_N];
    ull acc[16];

    // layer 1: 6 -> 32
#pragma unroll
    for (int q = 0; q < 16; q++) acc[q] = 0ull;
#pragma unroll
    for (int r = 0; r < FIVE_K; r++) {
        const ulonglong2* wr = reinterpret_cast<const ulonglong2*>(sW1 + r * HID_N);
        ull d = pdup(x[r]);
#pragma unroll
        for (int q = 0; q < 8; q++) {
            ulonglong2 w = wr[q];
            fma2(acc[2 * q],     d, w.x);
            fma2(acc[2 * q + 1], d, w.y);
        }
    }
#pragma unroll
    for (int q = 0; q < 16; q++) {
        float lo, hi; unpack2(acc[q], lo, hi);
        h[2 * q]     = fmaxf(lo, 0.f);
        h[2 * q + 1] = fmaxf(hi, 0.f);
    }

    // layers 2 and 3: 32 -> 32, in place
    const float* Ws[2] = { sW2, sW3 };
#pragma unroll
    for (int L = 0; L < 2; L++) {
        const float* SW = Ws[L];
#pragma unroll
        for (int q = 0; q < 16; q++) acc[q] = 0ull;
#pragma unroll
        for (int r = 0; r < HID_N; r++) {
            const ulonglong2* wr = reinterpret_cast<const ulonglong2*>(SW + r * HID_N);
            ull d = pdup(h[r]);
#pragma unroll
            for (int q = 0; q < 8; q++) {
                ulonglong2 w = wr[q];
                fma2(acc[2 * q],     d, w.x);
                fma2(acc[2 * q + 1], d, w.y);
            }
        }
#pragma unroll
        for (int q = 0; q < 16; q++) {
            float lo, hi; unpack2(acc[q], lo, hi);
            h[2 * q]     = fmaxf(lo, 0.f);
            h[2 * q + 1] = fmaxf(hi, 0.f);
        }
    }

    // layer 4: 32 -> 1
    ull s = 0ull;
    const ull* w4p = reinterpret_cast<const ull*>(sW4);
#pragma unroll
    for (int p = 0; p < 16; p++)
        fma2(s, pack2(h[2 * p], h[2 * p + 1]), w4p[p]);
    float l0, l1;
    unpack2(s, l0, l1);
    return l0 + l1;
}

// ---------------------------------------------------------------------------
// Fused kernel: one block (128 threads) per output unit o.
// Thread t handles batch elements t and t+128 SEQUENTIALLY (one live h/acc
// set). Weights staged via cp.async (zero-reg). launch_bounds(128,4): cap
// 128, structural need ~110 -> no spills, 4 blocks/SM target.
// ---------------------------------------------------------------------------
__global__ __launch_bounds__(128, 4)
void blayer_fused(const float* __restrict__ inputs,
                  const float* __restrict__ mask,
                  const float* __restrict__ W1,
                  const float* __restrict__ W2,
                  const float* __restrict__ W3,
                  const float* __restrict__ W4,
                  float* __restrict__ out)
{
    __shared__ float sW1[FIVE_K * HID_N];
    __shared__ float sW2[HID_N * HID_N];
    __shared__ float sW3[HID_N * HID_N];
    __shared__ float sW4[HID_N];
    __shared__ ull   sLists[4][6];
    __shared__ int   sIdx[FIVE_K];

    const int o    = blockIdx.x;
    const int tid  = threadIdx.x;
    const int warp = tid >> 5;
    const int lane = tid & 31;

    // -- stage dense weights via cp.async (no registers; hides under topk) --
    {
        const char* w2p = reinterpret_cast<const char*>(W2 + o * HID_N * HID_N);
        const char* w3p = reinterpret_cast<const char*>(W3 + o * HID_N * HID_N);
        unsigned s2 = smem_u32(sW2), s3 = smem_u32(sW3);
        cp_async16(s2 + tid * 16,          w2p + tid * 16);
        cp_async16(s2 + (tid + 128) * 16,  w2p + (tid + 128) * 16);
        cp_async16(s3 + tid * 16,          w3p + tid * 16);
        cp_async16(s3 + (tid + 128) * 16,  w3p + (tid + 128) * 16);
        if (tid < 8)
            cp_async16(smem_u32(sW4) + tid * 16,
                       reinterpret_cast<const char*>(W4 + o * HID_N) + tid * 16);
    }

    // -- cooperative top-6 of mask row o: 8 values per thread --
    const float4* mk4 = reinterpret_cast<const float4*>(mask + o * IN_N);
    float4 m0 = mk4[tid], m1 = mk4[tid + 128];

    ull a[6], bl[6];
    {
        ull k0 = mk_key(m0.x, 4 * tid + 0);
        ull k1 = mk_key(m0.y, 4 * tid + 1);
        ull k2 = mk_key(m0.z, 4 * tid + 2);
        ull k3 = mk_key(m0.w, 4 * tid + 3);
        ull k4 = mk_key(m1.x, 4 * (tid + 128) + 0);
        ull k5 = mk_key(m1.y, 4 * (tid + 128) + 1);
        ull k6 = mk_key(m1.z, 4 * (tid + 128) + 2);
        ull k7 = mk_key(m1.w, 4 * (tid + 128) + 3);
        sort4(k0, k1, k2, k3);
        sort4(k4, k5, k6, k7);
        a[0]  = k0; a[1]  = k1; a[2]  = k2; a[3]  = k3; a[4]  = 0; a[5]  = 0;
        bl[0] = k4; bl[1] = k5; bl[2] = k6; bl[3] = k7; bl[4] = 0; bl[5] = 0;
        merge6(a, bl);
    }
#pragma unroll
    for (int off = 16; off >= 1; off >>= 1) {
#pragma unroll
        for (int j = 0; j < 6; j++)
            bl[j] = __shfl_xor_sync(0xFFFFFFFFu, a[j], off);
        merge6(a, bl);
    }
    if (lane == 0) {
#pragma unroll
        for (int j = 0; j < 6; j++) sLists[warp][j] = a[j];
    }

    cp_async_wait_all();     // weights landed
    __syncthreads();         // sLists + weights visible

    // -- warp 0 merges the 4 warp lists --
    if (warp == 0) {
#pragma unroll
        for (int w = 1; w < 4; w++) {
#pragma unroll
            for (int j = 0; j < 6; j++) bl[j] = sLists[w][j];
            merge6(a, bl);
        }
        if (lane == 0) {
#pragma unroll
            for (int j = 0; j < 6; j++)
                sIdx[j] = 1023 - (int)(a[j] & 1023ull);
        }
    }
    __syncthreads();

    // -- W1 rows + the 6 input values for my two batch elements --
#pragma unroll
    for (int t = tid; t < FIVE_K * HID_N; t += 128) {
        int j = t >> 5, k = t & 31;
        sW1[t] = W1[(o * IN_N + sIdx[j]) * HID_N + k];
    }
    float xA[FIVE_K], xB[FIVE_K];
#pragma unroll
    for (int j = 0; j < FIVE_K; j++) {
        int ix = sIdx[j];
        xA[j] = inputs[tid * IN_N + ix];
        xB[j] = inputs[(tid + 128) * IN_N + ix];
    }
    __syncthreads();

    // -- MLP: elem A fully (store immediately: hA dies), then elem B --
    float zA = mlp_one(sW1, sW2, sW3, sW4, xA);
    out[tid * OUT_N + o] = (zA >= 0.f) ? 1.f : -1.f;

    float zB = mlp_one(sW1, sW2, sW3, sW4, xB);
    out[(tid + 128) * OUT_N + o] = (zB >= 0.f) ? 1.f : -1.f;
}

// ---------------------------------------------------------------------------
extern "C" void kernel_launch(void* const* d_in, const int* in_sizes, int n_in,
                              void* d_out, int out_size)
{
    const float* inputs = (const float*)d_in[0];  // (B, IN)
    const float* mask   = (const float*)d_in[1];  // (OUT, IN)
    const float* W1     = (const float*)d_in[2];  // (OUT, IN, HID)
    const float* W2     = (const float*)d_in[3];  // (OUT, HID, HID)
    const float* W3     = (const float*)d_in[4];  // (OUT, HID, HID)
    const float* W4     = (const float*)d_in[5];  // (OUT, HID, 1)
    float* out = (float*)d_out;                   // (B, OUT)

    blayer_fused<<<OUT_N, 128>>>(inputs, mask, W1, W2, W3, W4, out);
}